// round 5
// baseline (speedup 1.0000x reference)
#include <cuda_runtime.h>
#include <cuda_bf16.h>
#include <cstdint>

// ============================================================================
// Problem constants (shapes fixed by setup_inputs: N=M=8192, D=128)
// ============================================================================
#define DV      128
#define MAXROWS 8192
#define TILE    128

// bf16 copies + fp32 squared norms (device-global scratch; allowed)
__device__ __nv_bfloat16 g_anc_bf[MAXROWS * DV];
__device__ __nv_bfloat16 g_pn_bf[MAXROWS * DV];
__device__ float         g_anc2[MAXROWS];
__device__ float         g_pn2[MAXROWS];

// ============================================================================
// Kernel 1: fp32 -> bf16 conversion + exact fp32 squared row norms.
// ============================================================================
__global__ void prep_kernel(const float* __restrict__ anc, const float* __restrict__ pn,
                            int N, int M) {
    int warp = (blockIdx.x * blockDim.x + threadIdx.x) >> 5;
    int lane = threadIdx.x & 31;
    if (warp >= N + M) return;

    const float* src;
    __nv_bfloat16* dst;
    float* nrm;
    int row;
    if (warp < N) { row = warp;     src = anc + (size_t)row * DV; dst = g_anc_bf + (size_t)row * DV; nrm = g_anc2; }
    else          { row = warp - N; src = pn  + (size_t)row * DV; dst = g_pn_bf  + (size_t)row * DV; nrm = g_pn2;  }

    float4 v = reinterpret_cast<const float4*>(src)[lane];
    float s = v.x * v.x + v.y * v.y + v.z * v.z + v.w * v.w;

    __nv_bfloat162 p0 = __floats2bfloat162_rn(v.x, v.y);
    __nv_bfloat162 p1 = __floats2bfloat162_rn(v.z, v.w);
    reinterpret_cast<__nv_bfloat162*>(dst)[lane * 2 + 0] = p0;
    reinterpret_cast<__nv_bfloat162*>(dst)[lane * 2 + 1] = p1;

    #pragma unroll
    for (int o = 16; o; o >>= 1) s += __shfl_xor_sync(0xFFFFFFFFu, s, o);
    if (lane == 0) nrm[row] = s;
}

// ============================================================================
// Kernel 2: 128x128 tile per CTA, 4 warps, warp tile 64x64 (R5).
//  - cp.async tile loads (no LDG->reg->STS round trip)
//  - ldmatrix fragment loads; operand tiles each read by only 2 warps
//  - epilogue staged in SMEM (stride 136 floats: conflict-free STS.64/LDS.128)
//    then dense 128B STG.128 -> full L1 store wavefronts
// ============================================================================
#define SAS  136                             // bf16 elems per SMEM row (128+8 pad)
#define SASB (SAS * 2)                       // 272 bytes per row
#define EST  136                             // fp32 elems per staging row (8 mod 32)
static constexpr uint32_t SM_A     = 0;                    // 128*272 = 34816
static constexpr uint32_t SM_B     = 34816;                // 34816  (ends 69632)
static constexpr uint32_t SM_A2    = 69632;                // 512 B
static constexpr uint32_t SM_B2    = 70144;                // 512 B
static constexpr uint32_t SMEM_BYTES = 70656;
// epilogue staging reuses [0, 128*136*4 = 69632) after mainloop

__device__ __forceinline__ uint32_t smem_u32(const void* p) {
    uint32_t a;
    asm("{ .reg .u64 t; cvta.to.shared.u64 t, %1; cvt.u32.u64 %0, t; }" : "=r"(a) : "l"(p));
    return a;
}

__device__ __forceinline__ void cp_async16(uint32_t dst, const void* src) {
    asm volatile("cp.async.cg.shared.global [%0], [%1], 16;" :: "r"(dst), "l"(src));
}

__device__ __forceinline__ void ldsm_x4(uint32_t* r, uint32_t addr) {
    asm volatile("ldmatrix.sync.aligned.m8n8.x4.shared.b16 {%0,%1,%2,%3}, [%4];"
                 : "=r"(r[0]), "=r"(r[1]), "=r"(r[2]), "=r"(r[3]) : "r"(addr));
}

__device__ __forceinline__ void mma_bf16(float* c, const uint32_t* a, const uint32_t* b) {
    asm volatile(
        "mma.sync.aligned.m16n8k16.row.col.f32.bf16.bf16.f32 "
        "{%0,%1,%2,%3}, {%4,%5,%6,%7}, {%8,%9}, {%0,%1,%2,%3};"
        : "+f"(c[0]), "+f"(c[1]), "+f"(c[2]), "+f"(c[3])
        : "r"(a[0]), "r"(a[1]), "r"(a[2]), "r"(a[3]), "r"(b[0]), "r"(b[1]));
}

__global__ void __launch_bounds__(128, 2) gemm_kernel(float* __restrict__ out, int N, int M) {
    extern __shared__ char smem[];

    const int tid    = threadIdx.x;
    const int lid    = tid & 31;
    const int wid    = tid >> 5;
    const int warp_m = wid & 1;       // m offset 64*warp_m
    const int warp_n = wid >> 1;      // n offset 64*warp_n
    const int tj     = blockIdx.x;    // output col tile (pn rows)
    const int ti     = blockIdx.y;    // output row tile (anc rows)

    const uint32_t sbase = smem_u32(smem);

    // ---- Global -> SMEM via cp.async: 2 tiles x 2048 uint4 ----
    {
        const uint4* gA = reinterpret_cast<const uint4*>(g_anc_bf + (size_t)ti * TILE * DV);
        const uint4* gB = reinterpret_cast<const uint4*>(g_pn_bf  + (size_t)tj * TILE * DV);
        int c0 = tid & 15;            // uint4 column 0..15
        int r0 = tid >> 4;            // row 0..7
        #pragma unroll
        for (int it = 0; it < 16; it++) {
            int r = r0 + it * 8;
            uint32_t so = (uint32_t)(r * SASB + c0 * 16);
            cp_async16(sbase + SM_A + so, gA + r * 16 + c0);
            cp_async16(sbase + SM_B + so, gB + r * 16 + c0);
        }
        asm volatile("cp.async.commit_group;" ::: "memory");
        // norms (plain loads; overlap with async copies)
        reinterpret_cast<float*>(smem + SM_A2)[tid] = g_anc2[ti * TILE + tid];
        reinterpret_cast<float*>(smem + SM_B2)[tid] = g_pn2[tj * TILE + tid];
        asm volatile("cp.async.wait_group 0;" ::: "memory");
    }
    __syncthreads();

    // ---- ldmatrix base addresses ----
    // x4 block order for A tile (m16,k16): b0=(rows 0-7,k-lo16B) b1=(8-15,k-lo)
    //   b2=(0-7,k-hi) b3=(8-15,k-hi); thread t supplies row (t%8) of block t/8.
    const int t8 = lid & 7;
    const int bq = lid >> 3;          // block index 0..3
    uint32_t aaddr0, baddr[4];
    {
        int arow = warp_m * 64 + (bq & 1) * 8 + t8;
        uint32_t ak = (uint32_t)(bq >> 1) * 16;
        aaddr0 = sbase + SM_A + (uint32_t)arow * SASB + ak;
        // B pair p covers nt=2p,2p+1: b0=(n0-7,klo) b1=(n0-7,khi) b2=(n8-15,klo) b3=(n8-15,khi)
        int brow0 = warp_n * 64 + (bq >> 1) * 8 + t8;
        uint32_t bk = (uint32_t)(bq & 1) * 16;
        #pragma unroll
        for (int p = 0; p < 4; p++)
            baddr[p] = sbase + SM_B + (uint32_t)(brow0 + p * 16) * SASB + bk;
    }

    // ---- Mainloop: K = 8 x k16, warp tile 64x64 = 4(m16) x 8(n8) ----
    float acc[4][8][4];
    #pragma unroll
    for (int mt = 0; mt < 4; mt++)
        #pragma unroll
        for (int nt = 0; nt < 8; nt++)
            #pragma unroll
            for (int e = 0; e < 4; e++) acc[mt][nt][e] = 0.0f;

    #pragma unroll
    for (int ks = 0; ks < 8; ks++) {
        const uint32_t kb = (uint32_t)ks * 32;

        uint32_t afr[4][4];
        #pragma unroll
        for (int mt = 0; mt < 4; mt++)
            ldsm_x4(afr[mt], aaddr0 + (uint32_t)mt * (16u * SASB) + kb);

        uint32_t bfr[8][2];
        #pragma unroll
        for (int p = 0; p < 4; p++) {
            uint32_t q[4];
            ldsm_x4(q, baddr[p] + kb);
            bfr[2 * p][0]     = q[0]; bfr[2 * p][1]     = q[1];
            bfr[2 * p + 1][0] = q[2]; bfr[2 * p + 1][1] = q[3];
        }

        #pragma unroll
        for (int mt = 0; mt < 4; mt++)
            #pragma unroll
            for (int nt = 0; nt < 8; nt++)
                mma_bf16(acc[mt][nt], afr[mt], bfr[nt]);
    }

    // ---- Epilogue: fuse -sqrt(max(a2+b2-2ab,0)); stage -> dense STG.128 ----
    const int rq = lid >> 2;                         // 0..7
    const int cq = (lid & 3) * 2;                    // 0,2,4,6
    const int rb = warp_m * 64 + rq;
    const int cb = warp_n * 64 + cq;

    float a2r[4][2], b2c[8][2];
    {
        const float* a2s = reinterpret_cast<const float*>(smem + SM_A2);
        const float* b2s = reinterpret_cast<const float*>(smem + SM_B2);
        #pragma unroll
        for (int mt = 0; mt < 4; mt++) {
            a2r[mt][0] = a2s[rb + mt * 16];
            a2r[mt][1] = a2s[rb + mt * 16 + 8];
        }
        #pragma unroll
        for (int nt = 0; nt < 8; nt++) {
            b2c[nt][0] = b2s[cb + nt * 8];
            b2c[nt][1] = b2s[cb + nt * 8 + 1];
        }
    }
    __syncthreads();                   // operand tiles + norm reads done; reuse SMEM

    float* st = reinterpret_cast<float*>(smem);
    #pragma unroll
    for (int mt = 0; mt < 4; mt++) {
        #pragma unroll
        for (int nt = 0; nt < 8; nt++) {
            float v, q;
            float2 s0, s1;
            v = fmaxf(a2r[mt][0] + b2c[nt][0] - 2.0f * acc[mt][nt][0], 0.0f);
            asm("sqrt.approx.f32 %0, %1;" : "=f"(q) : "f"(v));
            s0.x = -q;
            v = fmaxf(a2r[mt][0] + b2c[nt][1] - 2.0f * acc[mt][nt][1], 0.0f);
            asm("sqrt.approx.f32 %0, %1;" : "=f"(q) : "f"(v));
            s0.y = -q;
            v = fmaxf(a2r[mt][1] + b2c[nt][0] - 2.0f * acc[mt][nt][2], 0.0f);
            asm("sqrt.approx.f32 %0, %1;" : "=f"(q) : "f"(v));
            s1.x = -q;
            v = fmaxf(a2r[mt][1] + b2c[nt][1] - 2.0f * acc[mt][nt][3], 0.0f);
            asm("sqrt.approx.f32 %0, %1;" : "=f"(q) : "f"(v));
            s1.y = -q;
            int r = rb + mt * 16;
            int c = cb + nt * 8;
            *reinterpret_cast<float2*>(st + r * EST + c)       = s0;
            *reinterpret_cast<float2*>(st + (r + 8) * EST + c) = s1;
        }
    }
    __syncthreads();

    // Dense write-out: each warp handles full 512B rows (STG.128)
    float* outp = out + (size_t)(ti * TILE) * M + tj * TILE;
    #pragma unroll
    for (int it = 0; it < 32; it++) {
        int r = wid + it * 4;
        float4 v = *reinterpret_cast<const float4*>(st + r * EST + lid * 4);
        *reinterpret_cast<float4*>(outp + (size_t)r * M + lid * 4) = v;
    }
}

// ============================================================================
// Launch
// ============================================================================
extern "C" void kernel_launch(void* const* d_in, const int* in_sizes, int n_in,
                              void* d_out, int out_size) {
    const float* anc = (const float*)d_in[0];   // z_anc      [N, 128]
    const float* pn  = (const float*)d_in[1];   // z_pos_neg  [M, 128]
    int N = in_sizes[0] / DV;
    int M = in_sizes[1] / DV;

    int warps  = N + M;
    int blocks = (warps + 7) / 8;               // 256 threads = 8 warps/block
    prep_kernel<<<blocks, 256>>>(anc, pn, N, M);

    cudaFuncSetAttribute(gemm_kernel, cudaFuncAttributeMaxDynamicSharedMemorySize,
                         SMEM_BYTES);
    dim3 grid(M / TILE, N / TILE);
    gemm_kernel<<<grid, 128, SMEM_BYTES>>>((float*)d_out, N, M);
}